// round 6
// baseline (speedup 1.0000x reference)
#include <cuda_runtime.h>
#include <math.h>
#include <stdint.h>

#define BATCH 8
#define TOTAL 21824
#define DETS  100
#define IMGF  1024.0f
#define STH   0.2f
#define NMST  0.6f
#define MAXB  256   // d_bucket capacity per (batch,class)
#define MAXW  192   // per-warp NMS working capacity (class mean ~41, 13-sigma safe)
#define CMAXO 1024  // contention capacity in finisher

// ---------------- scratch ----------------
__device__ unsigned long long d_keys[BATCH * TOTAL];
__device__ unsigned long long d_bucket[BATCH * 80 * MAXB];
__device__ int                d_ccnt[BATCH * 80];
__device__ unsigned long long d_sur[BATCH * 80 * DETS];
__device__ int                d_surn[BATCH * 80];
__device__ int                d_done[BATCH];

__device__ __forceinline__ float sigf(float x) { return 1.0f / (1.0f + expf(-x)); }

__device__ __forceinline__ float key_score(unsigned long long key) {
    unsigned uo = ~((unsigned)(key >> 32));
    unsigned bits = (uo & 0x80000000u) ? (uo ^ 0x80000000u) : (~uo);
    return __uint_as_float(bits);
}

__device__ __forceinline__ void bucket_push(int b, unsigned long long key) {
    int c = (int)(key & 127ULL);
    int pos = atomicAdd(&d_ccnt[b * 80 + c], 1);
    if (pos < MAXB) d_bucket[(size_t)(b * 80 + c) * MAXB + pos] = key;
}

// ---------------- K1: staged coalesced score + argmax -> 64-bit key ----------------
// key = (~orderable(score))<<32 | idx<<7 | label : ascending == (score desc, idx asc);
// keys globally distinct. Matches jax.lax.top_k stable tie order.
// 64 anchors per block; SMEM staging for fully-coalesced logits loads.
__global__ __launch_bounds__(256) void k_score(const float* __restrict__ logits,
                                               const float* __restrict__ ctr) {
    __shared__ float4 s4[64 * 20];  // 20 KB
    int tid = threadIdx.x;
    if (blockIdx.x == 0) {
        for (int i = tid; i < BATCH * 80; i += 256) d_ccnt[i] = 0;
        if (tid < BATCH) d_done[tid] = 0;
    }
    const float4* g = reinterpret_cast<const float4*>(logits) + (size_t)blockIdx.x * (64 * 20);
#pragma unroll
    for (int i = 0; i < 5; i++) s4[i * 256 + tid] = g[i * 256 + tid];
    __syncthreads();

    int la = tid >> 2;   // local anchor 0..63
    int q  = tid & 3;    // quarter: cols 20q..20q+19
    const float4* rowq = s4 + la * 20 + q * 5;
    float best = -1e30f;
    int bi = 0;
#pragma unroll
    for (int i = 0; i < 5; i++) {  // strict > keeps first-max within lane
        float4 v = rowq[i];
        int cb = q * 20 + i * 4;
        if (v.x > best) { best = v.x; bi = cb + 0; }
        if (v.y > best) { best = v.y; bi = cb + 1; }
        if (v.z > best) { best = v.z; bi = cb + 2; }
        if (v.w > best) { best = v.w; bi = cb + 3; }
    }
    // reduce over the 4 lanes of this anchor; tie -> lower column (= first occurrence)
#pragma unroll
    for (int o = 2; o >= 1; o >>= 1) {
        float ov = __shfl_down_sync(0xFFFFFFFFu, best, o);
        int   oc = __shfl_down_sync(0xFFFFFFFFu, bi, o);
        if (ov > best || (ov == best && oc < bi)) { best = ov; bi = oc; }
    }
    if (q == 0) {
        int ga = blockIdx.x * 64 + la;           // 21824 % 64 == 0: blocks never straddle
        float s = sqrtf(sigf(best) * sigf(ctr[ga]));
        float sm = (s > STH) ? s : -1.0f;
        unsigned u = __float_as_uint(sm);
        u ^= (u & 0x80000000u) ? 0xFFFFFFFFu : 0x80000000u;
        int i_loc = ga % TOTAL;
        d_keys[ga] = ((unsigned long long)(~u) << 32) |
                     ((unsigned)(i_loc << 7) | (unsigned)bi);
    }
}

// ---------------- K2: per (batch, level) exact top-k -> class-bucket scatter ----------
__global__ __launch_bounds__(1024, 1) void k_select() {
    extern __shared__ unsigned smx[];  // hi[n] then lo[n]
    const int LOFF[5] = {0, 16384, 20480, 21504, 21760};
    const int LN[5]   = {16384, 4096, 1024, 256, 64};
    const int LK[5]   = {1000, 1000, 1000, 256, 64};

    int b = blockIdx.x / 5, lvl = blockIdx.x % 5;
    int off = LOFF[lvl], n = LN[lvl], k = LK[lvl];
    int tid = threadIdx.x;
    const unsigned long long* kp = d_keys + b * TOTAL + off;

    if (k >= n) {  // levels 3,4: everything selected
        for (int i = tid; i < n; i += 1024) bucket_push(b, kp[i]);
        return;
    }

    unsigned* hi = smx;
    unsigned* lo = smx + n;

    __shared__ unsigned hist[256];
    __shared__ unsigned sh_prefix, sh_PH, sh_PL;
    __shared__ int sh_kneed, sh_state;
    if (tid == 0) sh_state = 0;
    for (int i = tid; i < 256; i += 1024) hist[i] = 0;
    __syncthreads();

    // load + fused pass-1 histogram (bits[24:32) of hi)
    for (int i = tid; i < n; i += 1024) {
        unsigned long long key = kp[i];
        unsigned h = (unsigned)(key >> 32);
        hi[i] = h;
        lo[i] = (unsigned)key;
        atomicAdd(&hist[h >> 24], 1u);
    }
    __syncthreads();

    unsigned prefix = 0, Sword = 0;
    int kneed = k, tie = 0;

    // ---- stage 0: radix on hi (score word) ----
    for (int shift = 24; shift >= 0; shift -= 8) {
        if (shift != 24) {
            for (int i = tid; i < 256; i += 1024) hist[i] = 0;
            __syncthreads();
            unsigned mhi = 0xFFFFFFFFu << (shift + 8);
            for (int i = tid; i < n; i += 1024) {
                unsigned h = hi[i];
                bool ok = ((h & mhi) == (prefix & mhi));
                unsigned active = __ballot_sync(0xFFFFFFFFu, ok);
                if (ok) {
                    unsigned dgt = (h >> shift) & 255u;
                    unsigned peers = __match_any_sync(active, dgt);
                    if ((int)(tid & 31) == __ffs(peers) - 1) atomicAdd(&hist[dgt], __popc(peers));
                }
            }
            __syncthreads();
        }
        if (tid < 32) {
            int running = 0, dsel = -1, cumbefore = 0;
#pragma unroll
            for (int c = 0; c < 8; c++) {
                int v = (int)hist[c * 32 + tid];
                int s = v;
#pragma unroll
                for (int o = 1; o < 32; o <<= 1) { int t2 = __shfl_up_sync(0xFFFFFFFFu, s, o); if (tid >= o) s += t2; }
                int total = __shfl_sync(0xFFFFFFFFu, s, 31);
                if (dsel < 0) {
                    unsigned flag = __ballot_sync(0xFFFFFFFFu, running + s >= kneed);
                    if (flag) {
                        int l = __ffs(flag) - 1;
                        dsel = c * 32 + l;
                        cumbefore = running + __shfl_sync(0xFFFFFFFFu, s, l) - __shfl_sync(0xFFFFFFFFu, v, l);
                    }
                }
                running += total;
            }
            if (tid == 0) {
                int cnt_d = (int)hist[dsel];
                int nk = kneed - cumbefore;
                if (cnt_d == nk) {
                    sh_PH = prefix | ((unsigned)dsel << shift) | (shift ? ((1u << shift) - 1u) : 0u);
                    sh_PL = 0xFFFFFFFFu;
                    sh_state = 2;
                } else if (shift == 0) {  // exact-score-word tie group
                    sh_prefix = prefix | (unsigned)dsel;
                    sh_kneed = nk;
                    sh_state = 1;
                } else {
                    sh_prefix = prefix | ((unsigned)dsel << shift);
                    sh_kneed = nk;
                    sh_state = 0;
                }
            }
        }
        __syncthreads();
        if (sh_state == 2) break;
        if (sh_state == 1) { tie = 1; Sword = sh_prefix; kneed = sh_kneed; break; }
        prefix = sh_prefix;
        kneed = sh_kneed;
    }

    // ---- stage 1 (rare): radix on lo within hi==Sword ----
    if (tie) {
        unsigned prefix2 = 0;
        for (int shift = 24; shift >= 0; shift -= 8) {
            for (int i = tid; i < 256; i += 1024) hist[i] = 0;
            __syncthreads();
            unsigned mhi = (shift == 24) ? 0u : (0xFFFFFFFFu << (shift + 8));
            for (int i = tid; i < n; i += 1024) {
                unsigned l2 = lo[i];
                bool ok = (hi[i] == Sword) && ((l2 & mhi) == (prefix2 & mhi));
                unsigned active = __ballot_sync(0xFFFFFFFFu, ok);
                if (ok) {
                    unsigned dgt = (l2 >> shift) & 255u;
                    unsigned peers = __match_any_sync(active, dgt);
                    if ((int)(tid & 31) == __ffs(peers) - 1) atomicAdd(&hist[dgt], __popc(peers));
                }
            }
            __syncthreads();
            if (tid < 32) {
                int running = 0, dsel = -1, cumbefore = 0;
#pragma unroll
                for (int c = 0; c < 8; c++) {
                    int v = (int)hist[c * 32 + tid];
                    int s = v;
#pragma unroll
                    for (int o = 1; o < 32; o <<= 1) { int t2 = __shfl_up_sync(0xFFFFFFFFu, s, o); if (tid >= o) s += t2; }
                    int total = __shfl_sync(0xFFFFFFFFu, s, 31);
                    if (dsel < 0) {
                        unsigned flag = __ballot_sync(0xFFFFFFFFu, running + s >= kneed);
                        if (flag) {
                            int l = __ffs(flag) - 1;
                            dsel = c * 32 + l;
                            cumbefore = running + __shfl_sync(0xFFFFFFFFu, s, l) - __shfl_sync(0xFFFFFFFFu, v, l);
                        }
                    }
                    running += total;
                }
                if (tid == 0) {
                    int cnt_d = (int)hist[dsel];
                    int nk = kneed - cumbefore;
                    if (cnt_d == nk || shift == 0) {
                        sh_PH = Sword;
                        sh_PL = prefix2 | ((unsigned)dsel << shift) |
                                ((cnt_d == nk && shift) ? ((1u << shift) - 1u) : 0u);
                        sh_state = 2;
                    } else {
                        sh_prefix = prefix2 | ((unsigned)dsel << shift);
                        sh_kneed = nk;
                        sh_state = 0;
                    }
                }
            }
            __syncthreads();
            if (sh_state == 2) break;
            prefix2 = sh_prefix;
            kneed = sh_kneed;
        }
    }

    unsigned PH = sh_PH, PL = sh_PL;  // exactly k keys: (hi<PH) || (hi==PH && lo<=PL)

    for (int i = tid; i < n; i += 1024) {
        unsigned h = hi[i];
        unsigned l2 = lo[i];
        if ((h < PH) || (h == PH && l2 <= PL))
            bucket_push(b, ((unsigned long long)h << 32) | l2);
    }
}

// ---------------- K3: 4 classes per block NMS + fused per-batch top-100 finisher --------
__global__ __launch_bounds__(128) void k_nms(const float* __restrict__ reg,
                                             const float* __restrict__ anchors,
                                             float* __restrict__ out) {
    __shared__ unsigned long long kb[4][256];
    __shared__ float4 bxs[4][MAXW];
    __shared__ float  ar[4][MAXW], sv[4][MAXW];
    __shared__ unsigned char rm[4][MAXW];
    // finisher-phase smem
    __shared__ int cnts[80];
    __shared__ unsigned hist[256];
    __shared__ unsigned long long cont[CMAXO];
    __shared__ unsigned long long win[DETS];
    __shared__ int sh_S, sh_cc, sh_cb, sh_before;
    __shared__ int isLast;

    int tid = threadIdx.x, lane = tid & 31, w = tid >> 5;
    int b = blockIdx.x / 20;
    int c = (blockIdx.x % 20) * 4 + w;
    int bc = b * 80 + c;

    int cnt = min(d_ccnt[bc], MAXW);
    for (int i = lane; i < cnt; i += 32)
        kb[w][i] = d_bucket[(size_t)bc * MAXB + i];
    __syncwarp();

    int wcnt = 0;
    if (cnt > 0) {
        // warp bitonic sort ascending (== score desc, idx asc)
        int m = 2; while (m < cnt) m <<= 1;
        for (int i = lane; i < m; i += 32) if (i >= cnt) kb[w][i] = ~0ULL;
        __syncwarp();
        for (int kk = 2; kk <= m; kk <<= 1)
            for (int jj = kk >> 1; jj > 0; jj >>= 1) {
                for (int cc = lane; cc < (m >> 1); cc += 32) {
                    int i1 = ((cc & ~(jj - 1)) << 1) | (cc & (jj - 1));
                    int l1 = i1 | jj;
                    bool up = ((i1 & kk) == 0);
                    unsigned long long a2 = kb[w][i1], d2 = kb[w][l1];
                    if ((a2 > d2) == up) { kb[w][i1] = d2; kb[w][l1] = a2; }
                }
                __syncwarp();
            }

        // decode
        for (int i = lane; i < cnt; i += 32) {
            unsigned long long key = kb[w][i];
            int idx = (int)((key >> 7) & 0x7FFFULL);
            sv[w][i] = key_score(key);
            rm[w][i] = 0;
            float4 an = reinterpret_cast<const float4*>(anchors)[idx];
            float cx = (an.x + an.z) * 0.5f, cy = (an.y + an.w) * 0.5f;
            float4 r = reinterpret_cast<const float4*>(reg)[(size_t)b * TOTAL + idx];
            float x1 = fminf(fmaxf(cx - r.x, 0.0f), IMGF);
            float y1 = fminf(fmaxf(cy - r.y, 0.0f), IMGF);
            float x2 = fminf(fmaxf(cx + r.z, 0.0f), IMGF);
            float y2 = fminf(fmaxf(cy + r.w, 0.0f), IMGF);
            bxs[w][i] = make_float4(x1, y1, x2, y2);
            ar[w][i] = fmaxf(x2 - x1, 0.0f) * fmaxf(y2 - y1, 0.0f);
        }
        __syncwarp();

        // greedy NMS
        for (int i = 0; i < cnt; i++) {
            if (sv[w][i] <= STH) break;
            if (rm[w][i]) continue;
            float4 bi = bxs[w][i];
            float ai = ar[w][i];
            for (int j = i + 1 + lane; j < cnt; j += 32) {
                float4 bj = bxs[w][j];
                float iw = fmaxf(fminf(bi.z, bj.z) - fmaxf(bi.x, bj.x), 0.0f);
                float ih = fmaxf(fminf(bi.w, bj.w) - fmaxf(bi.y, bj.y), 0.0f);
                float inter = iw * ih;
                float iou = inter / fmaxf(ai + ar[w][j] - inter, 1e-9f);
                if (iou > NMST) rm[w][j] = 1;
            }
            __syncwarp();
        }

        // sorted survivors -> global, capped at DETS
        for (int base = 0; base < cnt; base += 32) {
            int i = base + lane;
            bool acc = (i < cnt) && (sv[w][i] > STH) && !rm[w][i];
            unsigned bal = __ballot_sync(0xFFFFFFFFu, acc);
            int p = wcnt + __popc(bal & ((1u << lane) - 1));
            if (acc && p < DETS) d_sur[(size_t)bc * DETS + p] = kb[w][i];
            wcnt += __popc(bal);
        }
    }
    if (lane == 0) d_surn[bc] = min(wcnt, DETS);

    // ---- last block of this batch becomes the finisher ----
    __syncthreads();
    __threadfence();
    if (tid == 0) isLast = (atomicAdd(&d_done[b], 1) == 19);
    __syncthreads();
    if (!isLast) return;
    __threadfence();

    if (tid < 80) cnts[tid] = __ldcg(&d_surn[b * 80 + tid]);
    if (tid == 0) { sh_S = 0; sh_cc = 0; }
    __syncthreads();
    if (tid < 80) atomicAdd(&sh_S, cnts[tid]);
    __syncthreads();
    int S = sh_S;
    int ns = min(DETS, S);

    if (ns > 0) {
        // pass 1: histogram of bits[56:64)
        for (int i = tid; i < 256; i += 128) hist[i] = 0;
        __syncthreads();
        for (int i = tid; i < 80 * DETS; i += 128) {
            int cc = i / DETS, j = i % DETS;
            if (j < cnts[cc]) {
                unsigned long long key = __ldcg(&d_sur[(size_t)(b * 80 + cc) * DETS + j]);
                atomicAdd(&hist[(unsigned)(key >> 56)], 1u);
            }
        }
        __syncthreads();
        if (tid < 32) {
            int running = 0, dsel = -1, cumbefore = 0;
#pragma unroll
            for (int c2 = 0; c2 < 8; c2++) {
                int v = (int)hist[c2 * 32 + lane];
                int s = v;
#pragma unroll
                for (int o = 1; o < 32; o <<= 1) { int t = __shfl_up_sync(0xFFFFFFFFu, s, o); if (lane >= o) s += t; }
                int total = __shfl_sync(0xFFFFFFFFu, s, 31);
                if (dsel < 0) {
                    unsigned flag = __ballot_sync(0xFFFFFFFFu, running + s >= ns);
                    if (flag) {
                        int l = __ffs(flag) - 1;
                        dsel = c2 * 32 + l;
                        cumbefore = running + __shfl_sync(0xFFFFFFFFu, s, l) - __shfl_sync(0xFFFFFFFFu, v, l);
                    }
                }
                running += total;
            }
            if (lane == 0) { sh_cb = dsel; sh_before = cumbefore; }
        }
        __syncthreads();
        int cb0 = sh_cb, kneed1 = ns - sh_before;

        // pass 2: histogram of bits[48:56) within bucket cb0
        for (int i = tid; i < 256; i += 128) hist[i] = 0;
        __syncthreads();
        for (int i = tid; i < 80 * DETS; i += 128) {
            int cc = i / DETS, j = i % DETS;
            if (j < cnts[cc]) {
                unsigned long long key = __ldcg(&d_sur[(size_t)(b * 80 + cc) * DETS + j]);
                if ((int)(key >> 56) == cb0) atomicAdd(&hist[(unsigned)(key >> 48) & 255u], 1u);
            }
        }
        __syncthreads();
        if (tid < 32) {
            int running = 0, dsel = -1;
#pragma unroll
            for (int c2 = 0; c2 < 8; c2++) {
                int v = (int)hist[c2 * 32 + lane];
                int s = v;
#pragma unroll
                for (int o = 1; o < 32; o <<= 1) { int t = __shfl_up_sync(0xFFFFFFFFu, s, o); if (lane >= o) s += t; }
                int total = __shfl_sync(0xFFFFFFFFu, s, 31);
                if (dsel < 0) {
                    unsigned flag = __ballot_sync(0xFFFFFFFFu, running + s >= kneed1);
                    if (flag) dsel = c2 * 32 + (__ffs(flag) - 1);
                }
                running += total;
            }
            if (lane == 0) sh_cb = dsel;
        }
        __syncthreads();
        int cb1 = sh_cb;

        // contention set: keys that can possibly be in the global top-ns
        for (int i = tid; i < 80 * DETS; i += 128) {
            int cc = i / DETS, j = i % DETS;
            if (j < cnts[cc]) {
                unsigned long long key = __ldcg(&d_sur[(size_t)(b * 80 + cc) * DETS + j]);
                int b0 = (int)(key >> 56);
                int b1 = (int)((key >> 48) & 255ULL);
                if (b0 < cb0 || (b0 == cb0 && b1 <= cb1)) {
                    int p = atomicAdd(&sh_cc, 1);
                    if (p < CMAXO) cont[p] = key;
                }
            }
        }
        __syncthreads();
        int C = min(sh_cc, CMAXO);

        // exact rank within contention == global rank (outside keys are all larger)
        for (int t = tid; t < C; t += 128) {
            unsigned long long mk = cont[t];
            int r = 0;
            for (int q = 0; q < C; q++) r += (cont[q] < mk);
            if (r < ns) win[r] = mk;
        }
    }
    __syncthreads();

    // decode + write
    for (int t = tid; t < DETS; t += 128) {
        float* ob = out + ((size_t)b * DETS + t) * 4;
        if (t >= ns) {
            ob[0] = 0.0f; ob[1] = 0.0f; ob[2] = 0.0f; ob[3] = 0.0f;
            out[BATCH * DETS * 4 + b * DETS + t] = 0.0f;
            out[BATCH * DETS * 5 + b * DETS + t] = -1.0f;
        } else {
            unsigned long long key = win[t];
            int idx = (int)((key >> 7) & 0x7FFFULL);
            float4 an = reinterpret_cast<const float4*>(anchors)[idx];
            float cx = (an.x + an.z) * 0.5f, cy = (an.y + an.w) * 0.5f;
            float4 r = reinterpret_cast<const float4*>(reg)[(size_t)b * TOTAL + idx];
            float x1 = fminf(fmaxf(cx - r.x, 0.0f), IMGF);
            float y1 = fminf(fmaxf(cy - r.y, 0.0f), IMGF);
            float x2 = fminf(fmaxf(cx + r.z, 0.0f), IMGF);
            float y2 = fminf(fmaxf(cy + r.w, 0.0f), IMGF);
            ob[0] = x1; ob[1] = y1; ob[2] = x2; ob[3] = y2;
            out[BATCH * DETS * 4 + b * DETS + t] = key_score(key);
            out[BATCH * DETS * 5 + b * DETS + t] = (float)(key & 127ULL);
        }
    }
}

// ---------------- launch ----------------
extern "C" void kernel_launch(void* const* d_in, const int* in_sizes, int n_in,
                              void* d_out, int out_size) {
    const float* logits  = (const float*)d_in[0];  // (8, 21824, 80)
    const float* reg     = (const float*)d_in[1];  // (8, 21824, 4)
    const float* ctr     = (const float*)d_in[2];  // (8, 21824, 1)
    const float* anchors = (const float*)d_in[3];  // (21824, 4)
    float* out = (float*)d_out;

    cudaFuncSetAttribute(k_select, cudaFuncAttributeMaxDynamicSharedMemorySize, 131072);

    k_score<<<(BATCH * TOTAL) / 64, 256>>>(logits, ctr);
    k_select<<<BATCH * 5, 1024, 131072>>>();
    k_nms<<<BATCH * 20, 128>>>(reg, anchors, out);
}

// round 7
// speedup vs baseline: 1.4866x; 1.4866x over previous
#include <cuda_runtime.h>
#include <math.h>
#include <stdint.h>

#define BATCH 8
#define TOTAL 21824
#define DETS  100
#define IMGF  1024.0f
#define STH   0.2f
#define NMST  0.6f
#define MAXB  256    // bucket capacity per (batch,class)
#define BINN  4096   // quantization bins
#define BCAP  2048   // boundary-bin capacity (expected ~16)
#define OCAP  1024   // k_out contention capacity (expected ~110)

// ---------------- scratch ----------------
__device__ unsigned long long d_keys[BATCH * TOTAL];
__device__ unsigned long long d_bucket[BATCH * 80 * MAXB];
__device__ int                d_ccnt[BATCH * 80];
__device__ unsigned long long d_sur[BATCH * 80 * DETS];
__device__ int                d_surn[BATCH * 80];

__device__ __forceinline__ float sigf(float x) { return 1.0f / (1.0f + expf(-x)); }

__device__ __forceinline__ float key_score_hi(unsigned h) {
    unsigned uo = ~h;
    unsigned bits = (uo & 0x80000000u) ? (uo ^ 0x80000000u) : (~uo);
    return __uint_as_float(bits);
}
__device__ __forceinline__ float key_score(unsigned long long key) {
    return key_score_hi((unsigned)(key >> 32));
}
// monotone: higher score -> higher bin; masked (-1) -> bin 0
__device__ __forceinline__ int qbin(unsigned h) {
    float s = key_score_hi(h);
    return (s > 0.0f) ? min(BINN - 1, (int)(s * (float)BINN)) : 0;
}

__device__ __forceinline__ void bucket_push(int b, unsigned long long key) {
    int c = (int)(key & 127ULL);
    int pos = atomicAdd(&d_ccnt[b * 80 + c], 1);
    if (pos < MAXB) d_bucket[(size_t)(b * 80 + c) * MAXB + pos] = key;
}

// ---------------- K1: staged coalesced score + argmax -> 64-bit key ----------------
// key = (~orderable(score))<<32 | idx<<7 | label : ascending == (score desc, idx asc);
// keys globally distinct; matches jax.lax.top_k stable tie order.
__global__ __launch_bounds__(512) void k_score(const float* __restrict__ logits,
                                               const float* __restrict__ ctr) {
    __shared__ float4 s4[128 * 20];  // 40 KB
    int tid = threadIdx.x;
    if (blockIdx.x == 0) {
        for (int i = tid; i < BATCH * 80; i += 512) d_ccnt[i] = 0;
    }
    const float4* g = reinterpret_cast<const float4*>(logits) + (size_t)blockIdx.x * (128 * 20);
#pragma unroll
    for (int i = 0; i < 5; i++) s4[i * 512 + tid] = __ldcs(&g[i * 512 + tid]);
    __syncthreads();

    int la = tid >> 2;   // local anchor 0..127
    int q  = tid & 3;    // quarter: cols 20q..20q+19
    const float4* rowq = s4 + la * 20 + q * 5;
    float best = -1e30f;
    int bi = 0;
#pragma unroll
    for (int i = 0; i < 5; i++) {  // strict > keeps first-max within lane
        float4 v = rowq[i];
        int cb = q * 20 + i * 4;
        if (v.x > best) { best = v.x; bi = cb + 0; }
        if (v.y > best) { best = v.y; bi = cb + 1; }
        if (v.z > best) { best = v.z; bi = cb + 2; }
        if (v.w > best) { best = v.w; bi = cb + 3; }
    }
#pragma unroll
    for (int o = 2; o >= 1; o >>= 1) {  // tie -> lower column (= first occurrence)
        float ov = __shfl_down_sync(0xFFFFFFFFu, best, o);
        int   oc = __shfl_down_sync(0xFFFFFFFFu, bi, o);
        if (ov > best || (ov == best && oc < bi)) { best = ov; bi = oc; }
    }
    if (q == 0) {
        int ga = blockIdx.x * 128 + la;   // BATCH*TOTAL % 128 == 0
        float s = sqrtf(sigf(best) * sigf(ctr[ga]));
        float sm = (s > STH) ? s : -1.0f;
        unsigned u = __float_as_uint(sm);
        u ^= (u & 0x80000000u) ? 0xFFFFFFFFu : 0x80000000u;
        int i_loc = ga % TOTAL;
        d_keys[ga] = ((unsigned long long)(~u) << 32) |
                     ((unsigned)(i_loc << 7) | (unsigned)bi);
    }
}

// ---------------- K2: per (batch, level) exact top-k via quantized bins --------------
// One 4096-bin histogram on q(score) (monotone in key), suffix-scan to the boundary
// bin, exact 64-bit rank inside that bin -> pivot key. Selection is exact incl. ties.
__global__ __launch_bounds__(1024, 1) void k_select() {
    extern __shared__ unsigned smx[];  // hi[n] then lo[n]
    const int LOFF[5] = {0, 16384, 20480, 21504, 21760};
    const int LN[5]   = {16384, 4096, 1024, 256, 64};
    const int LK[5]   = {1000, 1000, 1000, 256, 64};

    int b = blockIdx.x / 5, lvl = blockIdx.x % 5;
    int off = LOFF[lvl], n = LN[lvl], k = LK[lvl];
    int tid = threadIdx.x, lane = tid & 31, wid = tid >> 5;
    const unsigned long long* kp = d_keys + b * TOTAL + off;

    if (k >= n) {  // levels 3,4: everything selected
        for (int i = tid; i < n; i += 1024) bucket_push(b, kp[i]);
        return;
    }

    unsigned* hi = smx;
    unsigned* lo = smx + n;
    __shared__ unsigned hist[BINN];
    __shared__ unsigned long long binkeys[BCAP];
    __shared__ unsigned long long sh_pivot;
    __shared__ int sh_Q, sh_kneed, sh_bc;
    __shared__ int warpsum[32];

    for (int i = tid; i < BINN; i += 1024) hist[i] = 0;
    if (tid == 0) sh_bc = 0;
    __syncthreads();

    // load + quantized histogram (warp-aggregated; n is a multiple of 1024)
    for (int i = tid; i < n; i += 1024) {
        unsigned long long key = kp[i];
        unsigned h = (unsigned)(key >> 32);
        hi[i] = h;
        lo[i] = (unsigned)key;
        int q = qbin(h);
        unsigned peers = __match_any_sync(0xFFFFFFFFu, q);
        if (lane == __ffs(peers) - 1) atomicAdd(&hist[q], __popc(peers));
    }
    __syncthreads();

    // descending-q cumulative scan: find boundary bin Q and kneed
    {
        int v0 = hist[BINN - 1 - (tid * 4 + 0)];
        int v1 = hist[BINN - 1 - (tid * 4 + 1)];
        int v2 = hist[BINN - 1 - (tid * 4 + 2)];
        int v3 = hist[BINN - 1 - (tid * 4 + 3)];
        int mysum = v0 + v1 + v2 + v3;
        int inc = mysum;
#pragma unroll
        for (int o = 1; o < 32; o <<= 1) { int t2 = __shfl_up_sync(0xFFFFFFFFu, inc, o); if (lane >= o) inc += t2; }
        if (lane == 31) warpsum[wid] = inc;
        __syncthreads();
        if (tid < 32) {
            int w = warpsum[tid], s = w;
#pragma unroll
            for (int o = 1; o < 32; o <<= 1) { int t2 = __shfl_up_sync(0xFFFFFFFFu, s, o); if (tid >= o) s += t2; }
            warpsum[tid] = s - w;  // exclusive
        }
        __syncthreads();
        int c = warpsum[wid] + inc - mysum;  // exclusive prefix for this thread
        int vv[4] = {v0, v1, v2, v3};
#pragma unroll
        for (int j = 0; j < 4; j++) {
            if (c < k && c + vv[j] >= k) {
                sh_Q = BINN - 1 - (tid * 4 + j);
                sh_kneed = k - c;
            }
            c += vv[j];
        }
    }
    __syncthreads();
    int Q = sh_Q, kneed = sh_kneed;

    // gather boundary bin
    for (int i = tid; i < n; i += 1024) {
        if (qbin(hi[i]) == Q) {
            int p = atomicAdd(&sh_bc, 1);
            if (p < BCAP) binkeys[p] = ((unsigned long long)hi[i] << 32) | lo[i];
        }
    }
    __syncthreads();
    int C = min(sh_bc, BCAP);

    // exact rank: pivot = (kneed-1)-th smallest key in bin (keys distinct)
    for (int t = tid; t < C; t += 1024) {
        unsigned long long mk = binkeys[t];
        int r = 0;
        for (int j2 = 0; j2 < C; j2++) r += (binkeys[j2] < mk);
        if (r == kneed - 1) sh_pivot = mk;
    }
    __syncthreads();
    unsigned long long pivot = sh_pivot;

    // scatter exactly k selected keys into class buckets
    for (int i = tid; i < n; i += 1024) {
        unsigned h = hi[i];
        int q = qbin(h);
        unsigned long long key = ((unsigned long long)h << 32) | lo[i];
        if (q > Q || (q == Q && key <= pivot)) bucket_push(b, key);
    }
}

// ---------------- K3: one warp per (batch,class): sort bucket, NMS, sorted survivors ----
__global__ __launch_bounds__(32) void k_nms(const float* __restrict__ reg,
                                            const float* __restrict__ anchors) {
    int bc = blockIdx.x, b = bc / 80;
    __shared__ unsigned long long kb[MAXB];
    __shared__ float4 bxs[MAXB];
    __shared__ float  ar[MAXB], sv[MAXB];
    __shared__ unsigned char rm[MAXB];
    int lane = threadIdx.x;

    int cnt = min(d_ccnt[bc], MAXB);
    if (cnt == 0) {
        if (lane == 0) d_surn[bc] = 0;
        return;
    }
    for (int i = lane; i < cnt; i += 32)
        kb[i] = d_bucket[(size_t)bc * MAXB + i];
    __syncwarp();

    // warp bitonic sort ascending (== score desc, idx asc)
    int m = 2; while (m < cnt) m <<= 1;
    for (int i = lane; i < m; i += 32) if (i >= cnt) kb[i] = ~0ULL;
    __syncwarp();
    for (int kk = 2; kk <= m; kk <<= 1)
        for (int jj = kk >> 1; jj > 0; jj >>= 1) {
            for (int cc = lane; cc < (m >> 1); cc += 32) {
                int i1 = ((cc & ~(jj - 1)) << 1) | (cc & (jj - 1));
                int l1 = i1 | jj;
                bool up = ((i1 & kk) == 0);
                unsigned long long a2 = kb[i1], d2 = kb[l1];
                if ((a2 > d2) == up) { kb[i1] = d2; kb[l1] = a2; }
            }
            __syncwarp();
        }

    // decode
    for (int i = lane; i < cnt; i += 32) {
        unsigned long long key = kb[i];
        int idx = (int)((key >> 7) & 0x7FFFULL);
        sv[i] = key_score(key);
        rm[i] = 0;
        float4 an = reinterpret_cast<const float4*>(anchors)[idx];
        float cx = (an.x + an.z) * 0.5f, cy = (an.y + an.w) * 0.5f;
        float4 r = reinterpret_cast<const float4*>(reg)[(size_t)b * TOTAL + idx];
        float x1 = fminf(fmaxf(cx - r.x, 0.0f), IMGF);
        float y1 = fminf(fmaxf(cy - r.y, 0.0f), IMGF);
        float x2 = fminf(fmaxf(cx + r.z, 0.0f), IMGF);
        float y2 = fminf(fmaxf(cy + r.w, 0.0f), IMGF);
        bxs[i] = make_float4(x1, y1, x2, y2);
        ar[i] = fmaxf(x2 - x1, 0.0f) * fmaxf(y2 - y1, 0.0f);
    }
    __syncwarp();

    // greedy NMS (masked scores sort last; suppressed boxes never suppress)
    for (int i = 0; i < cnt; i++) {
        if (sv[i] <= STH) break;
        if (rm[i]) continue;
        float4 bi = bxs[i];
        float ai = ar[i];
        for (int j = i + 1 + lane; j < cnt; j += 32) {
            float4 bj = bxs[j];
            float iw = fmaxf(fminf(bi.z, bj.z) - fmaxf(bi.x, bj.x), 0.0f);
            float ih = fmaxf(fminf(bi.w, bj.w) - fmaxf(bi.y, bj.y), 0.0f);
            float inter = iw * ih;
            float iou = inter / fmaxf(ai + ar[j] - inter, 1e-9f);
            if (iou > NMST) rm[j] = 1;
        }
        __syncwarp();
    }

    // sorted survivors, capped at DETS
    int wcnt = 0;
    for (int base = 0; base < cnt; base += 32) {
        int i = base + lane;
        bool acc = (i < cnt) && (sv[i] > STH) && !rm[i];
        unsigned bal = __ballot_sync(0xFFFFFFFFu, acc);
        int p = wcnt + __popc(bal & ((1u << lane) - 1));
        if (acc && p < DETS) d_sur[(size_t)bc * DETS + p] = kb[i];
        wcnt += __popc(bal);
    }
    if (lane == 0) d_surn[bc] = min(wcnt, DETS);
}

// ---------------- K4: per-batch top-100 via quantized bins + count-rank ---------------
__global__ __launch_bounds__(1024, 1) void k_out(const float* __restrict__ reg,
                                                 const float* __restrict__ anchors,
                                                 float* __restrict__ out) {
    extern __shared__ unsigned long long skey[];  // [8000]
    __shared__ int cnts[80];
    __shared__ unsigned hist[BINN];
    __shared__ unsigned long long cont[OCAP];
    __shared__ unsigned long long win[DETS];
    __shared__ int sh_S, sh_cc, sh_Q;
    __shared__ int warpsum[32];

    int b = blockIdx.x, tid = threadIdx.x, lane = tid & 31, wid = tid >> 5;

    if (tid < 80) cnts[tid] = d_surn[b * 80 + tid];
    if (tid == 0) { sh_S = 0; sh_cc = 0; sh_Q = -1; }
    for (int i = tid; i < BINN; i += 1024) hist[i] = 0;
    __syncthreads();
    if (tid < 80) atomicAdd(&sh_S, cnts[tid]);

    // stage survivors + histogram (invalid slots -> sentinel, not histogrammed)
    for (int i = tid; i < 80 * DETS; i += 1024) {
        int c = i / DETS, j = i % DETS;
        bool valid = (j < cnts[c]);
        unsigned long long key = valid ? d_sur[(size_t)(b * 80 + c) * DETS + j] : ~0ULL;
        skey[i] = key;
        if (valid) atomicAdd(&hist[qbin((unsigned)(key >> 32))], 1u);
    }
    __syncthreads();

    int S = sh_S;
    int ns = min(DETS, S);

    if (ns > 0) {
        // descending-q cumulative: find Q (first bin where cum >= ns)
        int v0 = hist[BINN - 1 - (tid * 4 + 0)];
        int v1 = hist[BINN - 1 - (tid * 4 + 1)];
        int v2 = hist[BINN - 1 - (tid * 4 + 2)];
        int v3 = hist[BINN - 1 - (tid * 4 + 3)];
        int mysum = v0 + v1 + v2 + v3;
        int inc = mysum;
#pragma unroll
        for (int o = 1; o < 32; o <<= 1) { int t2 = __shfl_up_sync(0xFFFFFFFFu, inc, o); if (lane >= o) inc += t2; }
        if (lane == 31) warpsum[wid] = inc;
        __syncthreads();
        if (tid < 32) {
            int w = warpsum[tid], s = w;
#pragma unroll
            for (int o = 1; o < 32; o <<= 1) { int t2 = __shfl_up_sync(0xFFFFFFFFu, s, o); if (tid >= o) s += t2; }
            warpsum[tid] = s - w;
        }
        __syncthreads();
        int c = warpsum[wid] + inc - mysum;
        int vv[4] = {v0, v1, v2, v3};
#pragma unroll
        for (int j = 0; j < 4; j++) {
            if (c < ns && c + vv[j] >= ns) sh_Q = BINN - 1 - (tid * 4 + j);
            c += vv[j];
        }
        __syncthreads();
        int Q = sh_Q;

        // contention = all q >= Q (contains the entire top-ns; others are larger keys)
        for (int i = tid; i < 80 * DETS; i += 1024) {
            unsigned long long key = skey[i];
            if (key != ~0ULL && qbin((unsigned)(key >> 32)) >= Q) {
                int p = atomicAdd(&sh_cc, 1);
                if (p < OCAP) cont[p] = key;
            }
        }
        __syncthreads();
        int C = min(sh_cc, OCAP);

        // exact rank within contention == global rank for r < ns
        for (int t = tid; t < C; t += 1024) {
            unsigned long long mk = cont[t];
            int r = 0;
            for (int q2 = 0; q2 < C; q2++) r += (cont[q2] < mk);
            if (r < ns) win[r] = mk;
        }
    }
    __syncthreads();

    // decode + write
    for (int t = tid; t < DETS; t += 1024) {
        float* ob = out + ((size_t)b * DETS + t) * 4;
        if (t >= ns) {
            ob[0] = 0.0f; ob[1] = 0.0f; ob[2] = 0.0f; ob[3] = 0.0f;
            out[BATCH * DETS * 4 + b * DETS + t] = 0.0f;
            out[BATCH * DETS * 5 + b * DETS + t] = -1.0f;
        } else {
            unsigned long long key = win[t];
            int idx = (int)((key >> 7) & 0x7FFFULL);
            float4 an = reinterpret_cast<const float4*>(anchors)[idx];
            float cx = (an.x + an.z) * 0.5f, cy = (an.y + an.w) * 0.5f;
            float4 r = reinterpret_cast<const float4*>(reg)[(size_t)b * TOTAL + idx];
            float x1 = fminf(fmaxf(cx - r.x, 0.0f), IMGF);
            float y1 = fminf(fmaxf(cy - r.y, 0.0f), IMGF);
            float x2 = fminf(fmaxf(cx + r.z, 0.0f), IMGF);
            float y2 = fminf(fmaxf(cy + r.w, 0.0f), IMGF);
            ob[0] = x1; ob[1] = y1; ob[2] = x2; ob[3] = y2;
            out[BATCH * DETS * 4 + b * DETS + t] = key_score(key);
            out[BATCH * DETS * 5 + b * DETS + t] = (float)(key & 127ULL);
        }
    }
}

// ---------------- launch ----------------
extern "C" void kernel_launch(void* const* d_in, const int* in_sizes, int n_in,
                              void* d_out, int out_size) {
    const float* logits  = (const float*)d_in[0];  // (8, 21824, 80)
    const float* reg     = (const float*)d_in[1];  // (8, 21824, 4)
    const float* ctr     = (const float*)d_in[2];  // (8, 21824, 1)
    const float* anchors = (const float*)d_in[3];  // (21824, 4)
    float* out = (float*)d_out;

    cudaFuncSetAttribute(k_select, cudaFuncAttributeMaxDynamicSharedMemorySize, 131072);
    cudaFuncSetAttribute(k_out, cudaFuncAttributeMaxDynamicSharedMemorySize, 64000);

    k_score<<<(BATCH * TOTAL) / 128, 512>>>(logits, ctr);
    k_select<<<BATCH * 5, 1024, 131072>>>();
    k_nms<<<BATCH * 80, 32>>>(reg, anchors);
    k_out<<<BATCH, 1024, 64000>>>(reg, anchors, out);
}